// round 6
// baseline (speedup 1.0000x reference)
#include <cuda_runtime.h>
#include <cuda_bf16.h>
#include <cstdint>
#include <math.h>

#define N_TOK 8192
#define C_DIM 1024
#define E_NUM 8
#define DFF_DIM 4096

// ---------------- scratch (round-2 proven pattern) ----------------------------
__device__ float g_h[(2 * N_TOK + 128) * DFF_DIM];   // fp32 gelu(x@w1) rows, bucketed
__device__ int   g_counts[E_NUM];
__device__ int   g_offsets[E_NUM];
__device__ int   g_tok[E_NUM * N_TOK];
__device__ float g_wgt[E_NUM * N_TOK];

// ---------------- helpers -----------------------------------------------------
__device__ __forceinline__ void mma_bf16(float* d, const uint32_t* a, const uint32_t* b) {
    asm volatile(
        "mma.sync.aligned.m16n8k16.row.col.f32.bf16.bf16.f32 "
        "{%0,%1,%2,%3}, {%4,%5,%6,%7}, {%8,%9}, {%0,%1,%2,%3};"
        : "+f"(d[0]), "+f"(d[1]), "+f"(d[2]), "+f"(d[3])
        : "r"(a[0]), "r"(a[1]), "r"(a[2]), "r"(a[3]), "r"(b[0]), "r"(b[1]));
}

// split two fp32 into packed bf16x2 hi and lo (lo = exact residual rounded)
__device__ __forceinline__ void split2(float a, float b, uint32_t& hi, uint32_t& lo) {
    __nv_bfloat16 ha = __float2bfloat16(a);
    __nv_bfloat16 hb = __float2bfloat16(b);
    __nv_bfloat16 la = __float2bfloat16(a - __bfloat162float(ha));
    __nv_bfloat16 lb = __float2bfloat16(b - __bfloat162float(hb));
    hi = (uint32_t)__bfloat16_as_ushort(ha) | ((uint32_t)__bfloat16_as_ushort(hb) << 16);
    lo = (uint32_t)__bfloat16_as_ushort(la) | ((uint32_t)__bfloat16_as_ushort(lb) << 16);
}

__device__ __forceinline__ float gelu_exact(float v) {
    return 0.5f * v * (1.0f + erff(v * 0.70710678118654752f));
}

// ---------------- small kernels (round-2 verbatim) -----------------------------
__global__ void zero_counts_kernel() {
    if (threadIdx.x < E_NUM) g_counts[threadIdx.x] = 0;
}
__global__ void zero_out_kernel(float* out, int n) {
    for (int i = blockIdx.x * blockDim.x + threadIdx.x; i < n; i += gridDim.x * blockDim.x)
        out[i] = 0.0f;
}
__global__ void offsets_kernel() {
    int run = 0;
    for (int e = 0; e < E_NUM; e++) { g_offsets[e] = run; run += g_counts[e]; }
}

__global__ void router_kernel(const float* __restrict__ x,
                              const float* __restrict__ rw,
                              const float* __restrict__ rb) {
    int t = blockIdx.x;
    int tid = threadIdx.x;
    __shared__ float red[128][E_NUM];
    float acc[E_NUM];
#pragma unroll
    for (int e = 0; e < E_NUM; e++) acc[e] = 0.0f;
    const float* xr = x + (size_t)t * C_DIM;
    for (int c = tid; c < C_DIM; c += 128) {
        float xv = xr[c];
        const float* w = &rw[c * E_NUM];
#pragma unroll
        for (int e = 0; e < E_NUM; e++) acc[e] += xv * w[e];
    }
#pragma unroll
    for (int e = 0; e < E_NUM; e++) red[tid][e] = acc[e];
    __syncthreads();
    for (int s = 64; s > 0; s >>= 1) {
        if (tid < s) {
#pragma unroll
            for (int e = 0; e < E_NUM; e++) red[tid][e] += red[tid + s][e];
        }
        __syncthreads();
    }
    if (tid == 0) {
        float lg[E_NUM], p[E_NUM];
        float mx = -1e30f;
#pragma unroll
        for (int e = 0; e < E_NUM; e++) { lg[e] = red[0][e] + rb[e]; mx = fmaxf(mx, lg[e]); }
        float sum = 0.0f;
#pragma unroll
        for (int e = 0; e < E_NUM; e++) { p[e] = expf(lg[e] - mx); sum += p[e]; }
        float inv = 1.0f / sum;
#pragma unroll
        for (int e = 0; e < E_NUM; e++) p[e] *= inv;
        int i1 = 0;
#pragma unroll
        for (int e = 1; e < E_NUM; e++) if (p[e] > p[i1]) i1 = e;
        int i2 = (i1 == 0) ? 1 : 0;
#pragma unroll
        for (int e = 0; e < E_NUM; e++) if (e != i1 && p[e] > p[i2]) i2 = e;
        int s1 = atomicAdd(&g_counts[i1], 1);
        g_tok[i1 * N_TOK + s1] = t;  g_wgt[i1 * N_TOK + s1] = p[i1];
        int s2 = atomicAdd(&g_counts[i2], 1);
        g_tok[i2 * N_TOK + s2] = t;  g_wgt[i2 * N_TOK + s2] = p[i2];
    }
}

// ---------------- HMMA GEMM, fragments loaded straight from global -------------
// CTA 128m x 128n, 8 warps (2m x 4n), warp tile 64x32 (4 mt x 4 nt).
// A: [row][k] fp32 (x for G1, g_h for G2), row gathered via srow_s.
// B: original untransposed weights, element (k,n) at B[k*NDIM + n].
// Per fragment slice (k16): load fp32, split to bf16 hi/lo in regs, 3-term MMA.
template <int KTOT, int NDIM, bool G1>
__global__ void __launch_bounds__(256, 1)
gemm_hmma(const float* __restrict__ A_g, const float* __restrict__ B_g,
          const float* __restrict__ bias_g, float* __restrict__ out) {
    __shared__ int   srow_s[128];
    __shared__ int   stok_s[128];
    __shared__ float swgt_s[128];

    int e = blockIdx.z;
    int cnt = g_counts[e];
    int m0 = blockIdx.y * 128;
    if (m0 >= cnt) return;
    int n0 = blockIdx.x * 128;
    int off = g_offsets[e];

    int tid = threadIdx.x, lane = tid & 31, wid = tid >> 5;
    int wm = wid >> 2, wn = wid & 3;
    int l4 = lane >> 2, lc = lane & 3;

    if (tid < 128) {
        int m = m0 + tid;
        int sr = 0, tk = 0; float wg = 0.0f;
        if (m < cnt) {
            tk = g_tok[e * N_TOK + m];
            wg = g_wgt[e * N_TOK + m];
            sr = G1 ? tk : (off + m);
        }
        srow_s[tid] = sr; stok_s[tid] = tk; swgt_s[tid] = wg;
    }
    __syncthreads();

    const float* Abase = G1 ? A_g : g_h;
    const float* Bp = B_g + (size_t)e * KTOT * NDIM + n0;
    const float* bias = bias_g + (size_t)e * NDIM + n0;

    // per-thread A row pointers (invalid rows point at row 0; results discarded)
    const float* arow[4][2];
#pragma unroll
    for (int mt = 0; mt < 4; mt++) {
        int r0 = wm * 64 + mt * 16 + l4;
        arow[mt][0] = Abase + (size_t)srow_s[r0] * KTOT;
        arow[mt][1] = Abase + (size_t)srow_s[r0 + 8] * KTOT;
    }
    int ncol[4];
#pragma unroll
    for (int nt = 0; nt < 4; nt++) ncol[nt] = wn * 32 + nt * 8 + l4;

    float acc[4][4][4];
#pragma unroll
    for (int a = 0; a < 4; a++)
#pragma unroll
        for (int b = 0; b < 4; b++)
#pragma unroll
            for (int c = 0; c < 4; c++) acc[a][b][c] = 0.0f;

    for (int kk = 0; kk < KTOT; kk += 16) {
        int k0 = kk + lc * 2;
        // ---- B fragments: B[k][n], col n fixed per nt ----
        uint32_t bh[4][2], bl[4][2];
#pragma unroll
        for (int nt = 0; nt < 4; nt++) {
            const float* bp = Bp + (size_t)k0 * NDIM + ncol[nt];
            float b00 = bp[0];
            float b01 = bp[NDIM];
            float b10 = bp[(size_t)8 * NDIM];
            float b11 = bp[(size_t)9 * NDIM];
            split2(b00, b01, bh[nt][0], bl[nt][0]);
            split2(b10, b11, bh[nt][1], bl[nt][1]);
        }
        // ---- A fragments + MMAs ----
#pragma unroll
        for (int mt = 0; mt < 4; mt++) {
            float2 a00 = *(const float2*)(arow[mt][0] + k0);      // (r,   k..k+1)
            float2 a10 = *(const float2*)(arow[mt][1] + k0);      // (r+8, k..k+1)
            float2 a01 = *(const float2*)(arow[mt][0] + k0 + 8);  // (r,   k+8..k+9)
            float2 a11 = *(const float2*)(arow[mt][1] + k0 + 8);  // (r+8, k+8..k+9)
            uint32_t ah[4], al[4];
            split2(a00.x, a00.y, ah[0], al[0]);
            split2(a10.x, a10.y, ah[1], al[1]);
            split2(a01.x, a01.y, ah[2], al[2]);
            split2(a11.x, a11.y, ah[3], al[3]);
#pragma unroll
            for (int nt = 0; nt < 4; nt++) {
                mma_bf16(acc[mt][nt], ah, bh[nt]);
                mma_bf16(acc[mt][nt], ah, bl[nt]);
                mma_bf16(acc[mt][nt], al, bh[nt]);
            }
        }
    }

    // ---- epilogue ----
#pragma unroll
    for (int mt = 0; mt < 4; mt++) {
#pragma unroll
        for (int half = 0; half < 2; half++) {
            int mrow = wm * 64 + mt * 16 + l4 + half * 8;
            if (m0 + mrow >= cnt) continue;
            if (G1) {
                float* hrow = g_h + (size_t)(off + m0 + mrow) * DFF_DIM + n0;
#pragma unroll
                for (int nt = 0; nt < 4; nt++) {
                    int c = wn * 32 + nt * 8 + lc * 2;
                    float v0 = gelu_exact(acc[mt][nt][half * 2 + 0] + bias[c]);
                    float v1 = gelu_exact(acc[mt][nt][half * 2 + 1] + bias[c + 1]);
                    *(float2*)(hrow + c) = make_float2(v0, v1);
                }
            } else {
                int tok = stok_s[mrow];
                float wgt = swgt_s[mrow];
                float* orow = out + (size_t)tok * C_DIM + n0;
#pragma unroll
                for (int nt = 0; nt < 4; nt++) {
                    int c = wn * 32 + nt * 8 + lc * 2;
                    atomicAdd(orow + c,     wgt * (acc[mt][nt][half * 2 + 0] + bias[c]));
                    atomicAdd(orow + c + 1, wgt * (acc[mt][nt][half * 2 + 1] + bias[c + 1]));
                }
            }
        }
    }
}

// ---------------- launch ------------------------------------------------------
extern "C" void kernel_launch(void* const* d_in, const int* in_sizes, int n_in,
                              void* d_out, int out_size) {
    const float* x  = (const float*)d_in[0];
    const float* rw = (const float*)d_in[1];
    const float* rb = (const float*)d_in[2];
    const float* w1 = (const float*)d_in[3];
    const float* b1 = (const float*)d_in[4];
    const float* w2 = (const float*)d_in[5];
    const float* b2 = (const float*)d_in[6];
    float* out = (float*)d_out;

    zero_counts_kernel<<<1, 32>>>();
    zero_out_kernel<<<512, 256>>>(out, N_TOK * C_DIM);
    router_kernel<<<N_TOK, 128>>>(x, rw, rb);
    offsets_kernel<<<1, 1>>>();

    {
        dim3 g(DFF_DIM / 128, N_TOK / 128, E_NUM);
        gemm_hmma<C_DIM, DFF_DIM, true><<<g, 256>>>(x, w1, b1, nullptr);
    }
    {
        dim3 g(C_DIM / 128, N_TOK / 128, E_NUM);
        gemm_hmma<DFF_DIM, C_DIM, false><<<g, 256>>>(nullptr, w2, b2, out);
    }
}

// round 10
// speedup vs baseline: 2.7939x; 2.7939x over previous
#include <cuda_runtime.h>
#include <cuda_bf16.h>
#include <cstdint>
#include <math.h>

#define N_TOK 8192
#define C_DIM 1024
#define E_NUM 8
#define DFF_DIM 4096
#define HROWS (2 * N_TOK + 128)

// ---------------- scratch (~270MB total — at the proven-passing level) --------
__device__ float g_h[HROWS * DFF_DIM];     // fp32 gelu(x@w1) rows, bucketed
__device__ int   g_counts[E_NUM];
__device__ int   g_offsets[E_NUM];
__device__ int   g_tok[E_NUM * N_TOK];
__device__ float g_wgt[E_NUM * N_TOK];

// ---------------- helpers -----------------------------------------------------
__device__ __forceinline__ void mma_bf16(float* d, const uint32_t* a, const uint32_t* b) {
    asm volatile(
        "mma.sync.aligned.m16n8k16.row.col.f32.bf16.bf16.f32 "
        "{%0,%1,%2,%3}, {%4,%5,%6,%7}, {%8,%9}, {%0,%1,%2,%3};"
        : "+f"(d[0]), "+f"(d[1]), "+f"(d[2]), "+f"(d[3])
        : "r"(a[0]), "r"(a[1]), "r"(a[2]), "r"(a[3]), "r"(b[0]), "r"(b[1]));
}

// truncation split of a pair: hi = top 16 bits (exact trunc), lo = exact residual
// (residual has <=7 mantissa bits -> exactly bf16-representable; no rounding).
__device__ __forceinline__ void tsplit2(float vx, float vy, uint32_t& hi, uint32_t& lo) {
    uint32_t ax = __float_as_uint(vx), ay = __float_as_uint(vy);
    float lx = vx - __uint_as_float(ax & 0xFFFF0000u);
    float ly = vy - __uint_as_float(ay & 0xFFFF0000u);
    hi = __byte_perm(ax, ay, 0x7632);
    lo = __byte_perm(__float_as_uint(lx), __float_as_uint(ly), 0x7632);
}

__device__ __forceinline__ float gelu_exact(float v) {
    return 0.5f * v * (1.0f + erff(v * 0.70710678118654752f));
}

// ---------------- small kernels (round-2/6 verbatim) ---------------------------
__global__ void zero_counts_kernel() {
    if (threadIdx.x < E_NUM) g_counts[threadIdx.x] = 0;
}
__global__ void zero_out_kernel(float* out, int n) {
    for (int i = blockIdx.x * blockDim.x + threadIdx.x; i < n; i += gridDim.x * blockDim.x)
        out[i] = 0.0f;
}
__global__ void offsets_kernel() {
    int run = 0;
    for (int e = 0; e < E_NUM; e++) { g_offsets[e] = run; run += g_counts[e]; }
}

__global__ void router_kernel(const float* __restrict__ x,
                              const float* __restrict__ rw,
                              const float* __restrict__ rb) {
    int t = blockIdx.x;
    int tid = threadIdx.x;
    __shared__ float red[128][E_NUM];
    float acc[E_NUM];
#pragma unroll
    for (int e = 0; e < E_NUM; e++) acc[e] = 0.0f;
    const float* xr = x + (size_t)t * C_DIM;
    for (int c = tid; c < C_DIM; c += 128) {
        float xv = xr[c];
        const float* w = &rw[c * E_NUM];
#pragma unroll
        for (int e = 0; e < E_NUM; e++) acc[e] += xv * w[e];
    }
#pragma unroll
    for (int e = 0; e < E_NUM; e++) red[tid][e] = acc[e];
    __syncthreads();
    for (int s = 64; s > 0; s >>= 1) {
        if (tid < s) {
#pragma unroll
            for (int e = 0; e < E_NUM; e++) red[tid][e] += red[tid + s][e];
        }
        __syncthreads();
    }
    if (tid == 0) {
        float lg[E_NUM], p[E_NUM];
        float mx = -1e30f;
#pragma unroll
        for (int e = 0; e < E_NUM; e++) { lg[e] = red[0][e] + rb[e]; mx = fmaxf(mx, lg[e]); }
        float sum = 0.0f;
#pragma unroll
        for (int e = 0; e < E_NUM; e++) { p[e] = expf(lg[e] - mx); sum += p[e]; }
        float inv = 1.0f / sum;
#pragma unroll
        for (int e = 0; e < E_NUM; e++) p[e] *= inv;
        int i1 = 0;
#pragma unroll
        for (int e = 1; e < E_NUM; e++) if (p[e] > p[i1]) i1 = e;
        int i2 = (i1 == 0) ? 1 : 0;
#pragma unroll
        for (int e = 0; e < E_NUM; e++) if (e != i1 && p[e] > p[i2]) i2 = e;
        int s1 = atomicAdd(&g_counts[i1], 1);
        g_tok[i1 * N_TOK + s1] = t;  g_wgt[i1 * N_TOK + s1] = p[i1];
        int s2 = atomicAdd(&g_counts[i2], 1);
        g_tok[i2 * N_TOK + s2] = t;  g_wgt[i2 * N_TOK + s2] = p[i2];
    }
}

// ---------------- HMMA GEMM with smem-staged packed fragments ------------------
// CTA 128m x 128n, stage k=32 (2 k16 slices). 8 warps (2m x 4n), warp tile 64x32.
// Staging: load fp32 tiles coalesced, truncation-split ONCE per element, store
// packed bf16x2 words (word j = k 2j,2j+1) in fragment order:
//   pos(w) = (w&3)*2 + (w>>2)  so words (lc, lc+4) are adjacent -> LDS.64.
// A smem: [slice][row][8 words]  pitch 8  (conflict-free LDS)
// B smem: [slice][n]  [8 words]  pitch 10 (even pitch for LDS.64 alignment)
template <int KTOT, int NDIM, bool G1>
__global__ void __launch_bounds__(256, 1)
gemm_hmma(const float* __restrict__ A_g, const float* __restrict__ B_g,
          const float* __restrict__ bias_g, float* __restrict__ out) {
    __shared__ __align__(16) uint32_t sAh[2 * 128 * 8];
    __shared__ __align__(16) uint32_t sAl[2 * 128 * 8];
    __shared__ __align__(16) uint32_t sBh[2 * 128 * 10];
    __shared__ __align__(16) uint32_t sBl[2 * 128 * 10];
    __shared__ int   srow_s[128];
    __shared__ int   stok_s[128];
    __shared__ float swgt_s[128];

    int e = blockIdx.z;
    int cnt = g_counts[e];
    int m0 = blockIdx.y * 128;
    if (m0 >= cnt) return;
    int n0 = blockIdx.x * 128;
    int off = g_offsets[e];

    int tid = threadIdx.x, lane = tid & 31, wid = tid >> 5;
    int wm = wid >> 2, wn = wid & 3;
    int l4 = lane >> 2, lc = lane & 3;

    if (tid < 128) {
        int m = m0 + tid;
        int sr = 0, tk = 0; float wg = 0.0f;
        if (m < cnt) {
            tk = g_tok[e * N_TOK + m];
            wg = g_wgt[e * N_TOK + m];
            sr = G1 ? tk : (off + m);
        }
        srow_s[tid] = sr; stok_s[tid] = tk; swgt_s[tid] = wg;
    }
    __syncthreads();

    const float* Abase = G1 ? A_g : g_h;
    const float* Bp = B_g + (size_t)e * KTOT * NDIM + n0;
    const float* bias = bias_g + (size_t)e * NDIM + n0;

    // ---- staging assignments (fixed per thread) ----
    // A: pair index pr = tid&15 (k = 2pr..2pr+1), rows r_i = (tid>>4) + 16*i
    // B: col nB = tid&127, pair pk_i = (tid>>7) + 2*i
    int prA = tid & 15;
    int sA = prA >> 3, wA = prA & 7;
    int posA = (wA & 3) * 2 + (wA >> 2);
    const float* aptr[8];
    int aws[8];
#pragma unroll
    for (int i = 0; i < 8; i++) {
        int r = (tid >> 4) + 16 * i;
        aptr[i] = Abase + (size_t)srow_s[r] * KTOT + 2 * prA;
        aws[i] = (sA * 128 + r) * 8 + posA;
    }
    int nB = tid & 127;
    const float* bptr[8];
    int bws[8];
#pragma unroll
    for (int i = 0; i < 8; i++) {
        int pk = (tid >> 7) + 2 * i;
        int sB = pk >> 3, wB = pk & 7;
        int posB = (wB & 3) * 2 + (wB >> 2);
        bptr[i] = Bp + (size_t)(2 * pk) * NDIM + nB;
        bws[i] = (sB * 128 + nB) * 10 + posB;
    }

    float acc[4][4][4];
#pragma unroll
    for (int a = 0; a < 4; a++)
#pragma unroll
        for (int b = 0; b < 4; b++)
#pragma unroll
            for (int c = 0; c < 4; c++) acc[a][b][c] = 0.0f;

    const int NS = KTOT / 32;
    float2 pa[8];
    float pbx[8], pby[8];
#pragma unroll
    for (int i = 0; i < 8; i++) pa[i] = *(const float2*)(aptr[i]);
#pragma unroll
    for (int i = 0; i < 8; i++) { pbx[i] = bptr[i][0]; pby[i] = bptr[i][NDIM]; }

    for (int s = 0; s < NS; s++) {
        __syncthreads();   // previous stage's fragment reads complete
#pragma unroll
        for (int i = 0; i < 8; i++) {
            uint32_t hi, lo;
            tsplit2(pa[i].x, pa[i].y, hi, lo);
            sAh[aws[i]] = hi;
            sAl[aws[i]] = lo;
        }
#pragma unroll
        for (int i = 0; i < 8; i++) {
            uint32_t hi, lo;
            tsplit2(pbx[i], pby[i], hi, lo);
            sBh[bws[i]] = hi;
            sBl[bws[i]] = lo;
        }
        __syncthreads();   // stage ready
        if (s + 1 < NS) {
            size_t ka = (size_t)(s + 1) * 32;
#pragma unroll
            for (int i = 0; i < 8; i++) pa[i] = *(const float2*)(aptr[i] + ka);
            size_t kb = ka * NDIM;
#pragma unroll
            for (int i = 0; i < 8; i++) {
                pbx[i] = *(bptr[i] + kb);
                pby[i] = *(bptr[i] + kb + NDIM);
            }
        }

#pragma unroll
        for (int ks = 0; ks < 2; ks++) {
            uint2 bh2[4], bl2[4];
#pragma unroll
            for (int nt = 0; nt < 4; nt++) {
                int n = wn * 32 + nt * 8 + l4;
                int wbi = (ks * 128 + n) * 10 + 2 * lc;
                bh2[nt] = *(const uint2*)&sBh[wbi];
                bl2[nt] = *(const uint2*)&sBl[wbi];
            }
#pragma unroll
            for (int mt = 0; mt < 4; mt++) {
                int r = wm * 64 + mt * 16 + l4;
                int wa0 = (ks * 128 + r) * 8 + 2 * lc;
                int wa1 = (ks * 128 + r + 8) * 8 + 2 * lc;
                uint2 h0 = *(const uint2*)&sAh[wa0];
                uint2 h1 = *(const uint2*)&sAh[wa1];
                uint2 l0 = *(const uint2*)&sAl[wa0];
                uint2 l1 = *(const uint2*)&sAl[wa1];
                uint32_t ah[4] = {h0.x, h1.x, h0.y, h1.y};
                uint32_t al[4] = {l0.x, l1.x, l0.y, l1.y};
#pragma unroll
                for (int nt = 0; nt < 4; nt++) {
                    uint32_t bh[2] = {bh2[nt].x, bh2[nt].y};
                    uint32_t bl[2] = {bl2[nt].x, bl2[nt].y};
                    mma_bf16(acc[mt][nt], ah, bh);
                    mma_bf16(acc[mt][nt], ah, bl);
                    mma_bf16(acc[mt][nt], al, bh);
                }
            }
        }
    }

    // ---- epilogue (round-6 verbatim) ----
#pragma unroll
    for (int mt = 0; mt < 4; mt++) {
#pragma unroll
        for (int half = 0; half < 2; half++) {
            int mrow = wm * 64 + mt * 16 + l4 + half * 8;
            if (m0 + mrow >= cnt) continue;
            if (G1) {
                float* hrow = g_h + (size_t)(off + m0 + mrow) * DFF_DIM + n0;
#pragma unroll
                for (int nt = 0; nt < 4; nt++) {
                    int c = wn * 32 + nt * 8 + lc * 2;
                    float v0 = gelu_exact(acc[mt][nt][half * 2 + 0] + bias[c]);
                    float v1 = gelu_exact(acc[mt][nt][half * 2 + 1] + bias[c + 1]);
                    *(float2*)(hrow + c) = make_float2(v0, v1);
                }
            } else {
                int tok = stok_s[mrow];
                float wgt = swgt_s[mrow];
                float* orow = out + (size_t)tok * C_DIM + n0;
#pragma unroll
                for (int nt = 0; nt < 4; nt++) {
                    int c = wn * 32 + nt * 8 + lc * 2;
                    atomicAdd(orow + c,     wgt * (acc[mt][nt][half * 2 + 0] + bias[c]));
                    atomicAdd(orow + c + 1, wgt * (acc[mt][nt][half * 2 + 1] + bias[c + 1]));
                }
            }
        }
    }
}

// ---------------- launch ------------------------------------------------------
extern "C" void kernel_launch(void* const* d_in, const int* in_sizes, int n_in,
                              void* d_out, int out_size) {
    const float* x  = (const float*)d_in[0];
    const float* rw = (const float*)d_in[1];
    const float* rb = (const float*)d_in[2];
    const float* w1 = (const float*)d_in[3];
    const float* b1 = (const float*)d_in[4];
    const float* w2 = (const float*)d_in[5];
    const float* b2 = (const float*)d_in[6];
    float* out = (float*)d_out;

    // order chosen so ncu (-s 5 -c 1) profiles gemm2 (6th launch)
    zero_counts_kernel<<<1, 32>>>();
    router_kernel<<<N_TOK, 128>>>(x, rw, rb);
    offsets_kernel<<<1, 1>>>();
    zero_out_kernel<<<512, 256>>>(out, N_TOK * C_DIM);

    {
        dim3 g(DFF_DIM / 128, N_TOK / 128, E_NUM);
        gemm_hmma<C_DIM, DFF_DIM, true><<<g, 256>>>(x, w1, b1, nullptr);
    }
    {
        dim3 g(C_DIM / 128, N_TOK / 128, E_NUM);
        gemm_hmma<DFF_DIM, C_DIM, false><<<g, 256>>>(nullptr, w2, b2, out);
    }
}